// round 1
// baseline (speedup 1.0000x reference)
#include <cuda_runtime.h>
#include <math.h>

#define BATCH 4
#define CH    64
#define NPIX  4096           // 64*64
#define NTOT  (BATCH*CH*NPIX)

// Scratch (allocation-free rule: __device__ globals)
__device__ float g_y[NTOT];              // conv+bias output, (B,C,N)
__device__ float g_fT[BATCH*NPIX*CH];    // feature transposed, (B,N,C)
__device__ float g_stats[2*CH];          // per-channel sum, sumsq

// ---------------------------------------------------------------------------
__global__ void k_init_stats() {
    int t = threadIdx.x;
    if (t < 2*CH) g_stats[t] = 0.0f;
}

// ---------------------------------------------------------------------------
// Conv 3x3 (SAME) + bias. One block per (c_out, b). Stages each input plane
// into a zero-padded 66x66 smem tile; each thread computes 16 pixels as four
// 4-wide strips (row loads reused across 3 taps). Also accumulates per-channel
// sum/sumsq for BN via block-reduce + atomics.
__global__ void __launch_bounds__(256) k_conv(const float* __restrict__ x,
                                              const float* __restrict__ w,
                                              const float* __restrict__ bvec) {
    __shared__ float xs[66*66];
    const int co = blockIdx.x, b = blockIdx.y;
    const int tid = threadIdx.x;

    // zero padded borders once (interior rewritten each ci)
    for (int i = tid; i < 66*66; i += 256) xs[i] = 0.0f;

    float acc[4][4];
#pragma unroll
    for (int s = 0; s < 4; s++)
#pragma unroll
        for (int e = 0; e < 4; e++) acc[s][e] = 0.0f;

    const float4* xb4 = reinterpret_cast<const float4*>(x + (size_t)b*CH*NPIX);

    for (int ci = 0; ci < CH; ci++) {
        __syncthreads();
        // stage plane (b, ci) into padded interior
#pragma unroll
        for (int k = 0; k < 4; k++) {
            int lin = tid + k*256;               // float4 index 0..1023
            float4 v = xb4[ci*1024 + lin];
            int h  = lin >> 4;
            int w0 = (lin & 15) << 2;
            float* dst = xs + (h+1)*66 + w0 + 1;
            dst[0] = v.x; dst[1] = v.y; dst[2] = v.z; dst[3] = v.w;
        }
        __syncthreads();

        const float* wp = w + (co*CH + ci)*9;
        float w00 = wp[0], w01 = wp[1], w02 = wp[2];
        float w10 = wp[3], w11 = wp[4], w12 = wp[5];
        float w20 = wp[6], w21 = wp[7], w22 = wp[8];

#pragma unroll
        for (int s = 0; s < 4; s++) {
            int pb = s*1024 + tid*4;
            int h  = pb >> 6;
            int w0 = pb & 63;
            const float* r0 = xs + h*66 + w0;        // padded row h-1, col w0-1
            const float* r1 = r0 + 66;
            const float* r2 = r1 + 66;
            float t0,t1,t2,t3,t4,t5;
            t0=r0[0]; t1=r0[1]; t2=r0[2]; t3=r0[3]; t4=r0[4]; t5=r0[5];
            acc[s][0] += t0*w00 + t1*w01 + t2*w02;
            acc[s][1] += t1*w00 + t2*w01 + t3*w02;
            acc[s][2] += t2*w00 + t3*w01 + t4*w02;
            acc[s][3] += t3*w00 + t4*w01 + t5*w02;
            t0=r1[0]; t1=r1[1]; t2=r1[2]; t3=r1[3]; t4=r1[4]; t5=r1[5];
            acc[s][0] += t0*w10 + t1*w11 + t2*w12;
            acc[s][1] += t1*w10 + t2*w11 + t3*w12;
            acc[s][2] += t2*w10 + t3*w11 + t4*w12;
            acc[s][3] += t3*w10 + t4*w11 + t5*w12;
            t0=r2[0]; t1=r2[1]; t2=r2[2]; t3=r2[3]; t4=r2[4]; t5=r2[5];
            acc[s][0] += t0*w20 + t1*w21 + t2*w22;
            acc[s][1] += t1*w20 + t2*w21 + t3*w22;
            acc[s][2] += t2*w20 + t3*w21 + t4*w22;
            acc[s][3] += t3*w20 + t4*w21 + t5*w22;
        }
    }

    const float cb = bvec[co];
    float s1 = 0.0f, s2 = 0.0f;
    float4* yp4 = reinterpret_cast<float4*>(g_y + (size_t)(b*CH + co)*NPIX);
#pragma unroll
    for (int s = 0; s < 4; s++) {
        float v0 = acc[s][0] + cb, v1 = acc[s][1] + cb;
        float v2 = acc[s][2] + cb, v3 = acc[s][3] + cb;
        yp4[s*256 + tid] = make_float4(v0, v1, v2, v3);
        s1 += v0+v1+v2+v3;
        s2 += v0*v0 + v1*v1 + v2*v2 + v3*v3;
    }
    // block reduce -> atomics
#pragma unroll
    for (int m = 16; m >= 1; m >>= 1) {
        s1 += __shfl_xor_sync(0xffffffffu, s1, m);
        s2 += __shfl_xor_sync(0xffffffffu, s2, m);
    }
    __syncthreads();                       // done reading xs; reuse for reduction
    if ((tid & 31) == 0) { xs[tid>>5] = s1; xs[8 + (tid>>5)] = s2; }
    __syncthreads();
    if (tid == 0) {
        float a1 = 0.0f, a2 = 0.0f;
        for (int i = 0; i < 8; i++) { a1 += xs[i]; a2 += xs[8+i]; }
        atomicAdd(&g_stats[co],    a1);
        atomicAdd(&g_stats[CH+co], a2);
    }
}

// ---------------------------------------------------------------------------
// BN (training batch stats) + PReLU, writing transposed feature fT (B,N,C).
__global__ void __launch_bounds__(256) k_bnt(const float* __restrict__ scale,
                                             const float* __restrict__ bias,
                                             const float* __restrict__ pa) {
    __shared__ float tile[64][65];
    __shared__ float msc[64], mof[64];
    const int b = blockIdx.y;
    const int i0 = blockIdx.x * 64;
    const int tid = threadIdx.x;
    const float a = pa[0];
    if (tid < 64) {
        const float inv = 1.0f / (float)(BATCH * NPIX);
        float m = g_stats[tid] * inv;
        float v = g_stats[CH + tid] * inv - m*m;
        float r = rsqrtf(v + 1e-5f);
        msc[tid] = r * scale[tid];
        mof[tid] = bias[tid] - m * r * scale[tid];
    }
    __syncthreads();
#pragma unroll
    for (int k = 0; k < 16; k++) {
        int idx = tid + k*256;
        int c = idx >> 6, ii = idx & 63;
        float v = g_y[(size_t)(b*CH + c)*NPIX + i0 + ii];
        v = v * msc[c] + mof[c];
        v = (v >= 0.0f) ? v : a * v;
        tile[c][ii] = v;
    }
    __syncthreads();
#pragma unroll
    for (int k = 0; k < 16; k++) {
        int idx = tid + k*256;
        int ii = idx >> 6, c = idx & 63;
        g_fT[((size_t)b*NPIX + i0 + ii)*CH + c] = tile[c][ii];
    }
}

// ---------------------------------------------------------------------------
// Flash attention: per block one (batch, 64-row i-tile). scores = -Q.K,
// online softmax, O += P.V with V = K tile. 256 threads, 4x4 micro-tiles.
// Smem: Qs [i][c-chunk] (float4), Ks chunked [c4][swizzled j] (float4),
// Ps [i][j-chunk] (float4). 48 KB dynamic.
__device__ __forceinline__ int jperm(int j) { return ((j & 7) << 3) | (j >> 3); }

__global__ void __launch_bounds__(256) k_attn(const float* __restrict__ gamma_p,
                                              float* __restrict__ out) {
    extern __shared__ float sm[];
    float4* Qs4 = reinterpret_cast<float4*>(sm);           // 1024 float4
    float4* Ks4 = reinterpret_cast<float4*>(sm + 4096);    // 1024 float4
    float4* Ps4 = reinterpret_cast<float4*>(sm + 8192);    // 1024 float4
    const float* Qsf = sm;

    const int b  = blockIdx.y;
    const int i0 = blockIdx.x * 64;
    const int tid = threadIdx.x;
    const int tx = tid & 15, ty = tid >> 4;

    const float4* fT4 = reinterpret_cast<const float4*>(g_fT + (size_t)b*NPIX*CH);

    // stage Q (rows i0..i0+63), layout Qs4[i*16 + c4]
#pragma unroll
    for (int k = 0; k < 4; k++) {
        int lin = tid + k*256;
        Qs4[lin] = fT4[(size_t)(i0 + (lin >> 4))*16 + (lin & 15)];
    }

    int pj[4];
#pragma unroll
    for (int q = 0; q < 4; q++) pj[q] = jperm(4*tx + q);

    float m[4], l[4], O[4][4];
#pragma unroll
    for (int r = 0; r < 4; r++) {
        m[r] = -INFINITY; l[r] = 0.0f;
#pragma unroll
        for (int e = 0; e < 4; e++) O[r][e] = 0.0f;
    }

    for (int jt = 0; jt < 64; jt++) {
        __syncthreads();   // prior PV finished before K overwrite
#pragma unroll
        for (int k = 0; k < 4; k++) {
            int lin = tid + k*256;
            int j = lin >> 4, c4 = lin & 15;
            Ks4[c4*64 + (jperm(j) ^ (c4 & 7))] = fT4[(size_t)(jt*64 + j)*16 + c4];
        }
        __syncthreads();

        // S = Q . K^T (accumulate dot, negate below)
        float acc[4][4];
#pragma unroll
        for (int r = 0; r < 4; r++)
#pragma unroll
            for (int q = 0; q < 4; q++) acc[r][q] = 0.0f;
#pragma unroll
        for (int c4 = 0; c4 < 16; c4++) {
            float4 qf[4], kf[4];
#pragma unroll
            for (int r = 0; r < 4; r++) qf[r] = Qs4[(4*ty + r)*16 + c4];
#pragma unroll
            for (int q = 0; q < 4; q++) kf[q] = Ks4[c4*64 + (pj[q] ^ (c4 & 7))];
#pragma unroll
            for (int r = 0; r < 4; r++)
#pragma unroll
                for (int q = 0; q < 4; q++) {
                    acc[r][q] += qf[r].x*kf[q].x + qf[r].y*kf[q].y
                               + qf[r].z*kf[q].z + qf[r].w*kf[q].w;
                }
        }

        // online softmax of s = -acc over j (row-wise across the 16 tx lanes)
#pragma unroll
        for (int r = 0; r < 4; r++) {
            float s0 = -acc[r][0], s1v = -acc[r][1], s2v = -acc[r][2], s3v = -acc[r][3];
            float lm = fmaxf(fmaxf(s0, s1v), fmaxf(s2v, s3v));
#pragma unroll
            for (int msk = 1; msk < 16; msk <<= 1)
                lm = fmaxf(lm, __shfl_xor_sync(0xffffffffu, lm, msk));
            float mn = fmaxf(m[r], lm);
            float alpha = __expf(m[r] - mn);
            float p0 = __expf(s0 - mn), p1 = __expf(s1v - mn);
            float p2 = __expf(s2v - mn), p3 = __expf(s3v - mn);
            float lp = p0 + p1 + p2 + p3;
#pragma unroll
            for (int msk = 1; msk < 16; msk <<= 1)
                lp += __shfl_xor_sync(0xffffffffu, lp, msk);
            l[r] = l[r] * alpha + lp;
            m[r] = mn;
#pragma unroll
            for (int e = 0; e < 4; e++) O[r][e] *= alpha;
            Ps4[(4*ty + r)*16 + tx] = make_float4(p0, p1, p2, p3);
        }
        __syncthreads();

        // O += P . V   (V[j][c] = K tile)
#pragma unroll
        for (int j4 = 0; j4 < 16; j4++) {
            float4 pf[4], vf[4];
#pragma unroll
            for (int r = 0; r < 4; r++) pf[r] = Ps4[(4*ty + r)*16 + j4];
#pragma unroll
            for (int jj = 0; jj < 4; jj++) {
                int j = 4*j4 + jj;
                vf[jj] = Ks4[tx*64 + (jperm(j) ^ (tx & 7))];
            }
#pragma unroll
            for (int r = 0; r < 4; r++) {
                O[r][0] += pf[r].x*vf[0].x + pf[r].y*vf[1].x + pf[r].z*vf[2].x + pf[r].w*vf[3].x;
                O[r][1] += pf[r].x*vf[0].y + pf[r].y*vf[1].y + pf[r].z*vf[2].y + pf[r].w*vf[3].y;
                O[r][2] += pf[r].x*vf[0].z + pf[r].y*vf[1].z + pf[r].z*vf[2].z + pf[r].w*vf[3].z;
                O[r][3] += pf[r].x*vf[0].w + pf[r].y*vf[1].w + pf[r].z*vf[2].w + pf[r].w*vf[3].w;
            }
        }
    }

    // epilogue: out[b][c][i] = gamma * O/l + feat   (feat read back from Qs)
    const float g = gamma_p[0];
    float ginv[4];
#pragma unroll
    for (int r = 0; r < 4; r++) ginv[r] = g / l[r];
#pragma unroll
    for (int e = 0; e < 4; e++) {
        int c = 4*tx + e;
        float4 v;
        v.x = O[0][e]*ginv[0] + Qsf[(4*ty + 0)*64 + c];
        v.y = O[1][e]*ginv[1] + Qsf[(4*ty + 1)*64 + c];
        v.z = O[2][e]*ginv[2] + Qsf[(4*ty + 2)*64 + c];
        v.w = O[3][e]*ginv[3] + Qsf[(4*ty + 3)*64 + c];
        float* dst = out + (size_t)(b*CH + c)*NPIX + i0 + 4*ty;
        *reinterpret_cast<float4*>(dst) = v;
    }
}

// ---------------------------------------------------------------------------
extern "C" void kernel_launch(void* const* d_in, const int* in_sizes, int n_in,
                              void* d_out, int out_size) {
    const float* x     = (const float*)d_in[0];
    const float* cw    = (const float*)d_in[1];
    const float* cb    = (const float*)d_in[2];
    const float* bns   = (const float*)d_in[3];
    const float* bnb   = (const float*)d_in[4];
    const float* pa    = (const float*)d_in[5];
    const float* gamma = (const float*)d_in[6];
    float* out = (float*)d_out;

    static bool attr_done = false;
    if (!attr_done) {
        cudaFuncSetAttribute(k_attn, cudaFuncAttributeMaxDynamicSharedMemorySize, 49152);
        attr_done = true;
    }

    k_init_stats<<<1, 128>>>();
    k_conv<<<dim3(CH, BATCH), 256>>>(x, cw, cb);
    k_bnt<<<dim3(64, BATCH), 256>>>(bns, bnb, pa);
    k_attn<<<dim3(64, BATCH), 256, 49152>>>(gamma, out);
}

// round 2
// speedup vs baseline: 1.0018x; 1.0018x over previous
#include <cuda_runtime.h>
#include <math.h>

#define BATCH 4
#define CH    64
#define NPIX  4096           // 64*64
#define NTOT  (BATCH*CH*NPIX)

// Scratch (allocation-free rule: __device__ globals)
__device__ float g_y[NTOT];              // conv+bias output, (B,C,N)
__device__ float g_fT[BATCH*NPIX*CH];    // feature transposed, (B,N,C)
__device__ float g_stats[2*CH];          // per-channel sum, sumsq

// ---------------------------------------------------------------------------
__global__ void k_init_stats() {
    int t = threadIdx.x;
    if (t < 2*CH) g_stats[t] = 0.0f;
}

// ---------------------------------------------------------------------------
// Conv 3x3 (SAME) + bias. One block per (c_out, b). Stages each input plane
// into a zero-padded 66x66 smem tile; each thread computes 16 pixels as four
// 4-wide strips (row loads reused across 3 taps). Also accumulates per-channel
// sum/sumsq for BN via block-reduce + atomics.
__global__ void __launch_bounds__(256) k_conv(const float* __restrict__ x,
                                              const float* __restrict__ w,
                                              const float* __restrict__ bvec) {
    __shared__ float xs[66*66];
    const int co = blockIdx.x, b = blockIdx.y;
    const int tid = threadIdx.x;

    // zero padded borders once (interior rewritten each ci)
    for (int i = tid; i < 66*66; i += 256) xs[i] = 0.0f;

    float acc[4][4];
#pragma unroll
    for (int s = 0; s < 4; s++)
#pragma unroll
        for (int e = 0; e < 4; e++) acc[s][e] = 0.0f;

    const float4* xb4 = reinterpret_cast<const float4*>(x + (size_t)b*CH*NPIX);

    for (int ci = 0; ci < CH; ci++) {
        __syncthreads();
        // stage plane (b, ci) into padded interior
#pragma unroll
        for (int k = 0; k < 4; k++) {
            int lin = tid + k*256;               // float4 index 0..1023
            float4 v = xb4[ci*1024 + lin];
            int h  = lin >> 4;
            int w0 = (lin & 15) << 2;
            float* dst = xs + (h+1)*66 + w0 + 1;
            dst[0] = v.x; dst[1] = v.y; dst[2] = v.z; dst[3] = v.w;
        }
        __syncthreads();

        const float* wp = w + (co*CH + ci)*9;
        float w00 = wp[0], w01 = wp[1], w02 = wp[2];
        float w10 = wp[3], w11 = wp[4], w12 = wp[5];
        float w20 = wp[6], w21 = wp[7], w22 = wp[8];

#pragma unroll
        for (int s = 0; s < 4; s++) {
            int pb = s*1024 + tid*4;
            int h  = pb >> 6;
            int w0 = pb & 63;
            const float* r0 = xs + h*66 + w0;        // padded row h-1, col w0-1
            const float* r1 = r0 + 66;
            const float* r2 = r1 + 66;
            float t0,t1,t2,t3,t4,t5;
            t0=r0[0]; t1=r0[1]; t2=r0[2]; t3=r0[3]; t4=r0[4]; t5=r0[5];
            acc[s][0] += t0*w00 + t1*w01 + t2*w02;
            acc[s][1] += t1*w00 + t2*w01 + t3*w02;
            acc[s][2] += t2*w00 + t3*w01 + t4*w02;
            acc[s][3] += t3*w00 + t4*w01 + t5*w02;
            t0=r1[0]; t1=r1[1]; t2=r1[2]; t3=r1[3]; t4=r1[4]; t5=r1[5];
            acc[s][0] += t0*w10 + t1*w11 + t2*w12;
            acc[s][1] += t1*w10 + t2*w11 + t3*w12;
            acc[s][2] += t2*w10 + t3*w11 + t4*w12;
            acc[s][3] += t3*w10 + t4*w11 + t5*w12;
            t0=r2[0]; t1=r2[1]; t2=r2[2]; t3=r2[3]; t4=r2[4]; t5=r2[5];
            acc[s][0] += t0*w20 + t1*w21 + t2*w22;
            acc[s][1] += t1*w20 + t2*w21 + t3*w22;
            acc[s][2] += t2*w20 + t3*w21 + t4*w22;
            acc[s][3] += t3*w20 + t4*w21 + t5*w22;
        }
    }

    const float cb = bvec[co];
    float s1 = 0.0f, s2 = 0.0f;
    float4* yp4 = reinterpret_cast<float4*>(g_y + (size_t)(b*CH + co)*NPIX);
#pragma unroll
    for (int s = 0; s < 4; s++) {
        float v0 = acc[s][0] + cb, v1 = acc[s][1] + cb;
        float v2 = acc[s][2] + cb, v3 = acc[s][3] + cb;
        yp4[s*256 + tid] = make_float4(v0, v1, v2, v3);
        s1 += v0+v1+v2+v3;
        s2 += v0*v0 + v1*v1 + v2*v2 + v3*v3;
    }
    // block reduce -> atomics
#pragma unroll
    for (int m = 16; m >= 1; m >>= 1) {
        s1 += __shfl_xor_sync(0xffffffffu, s1, m);
        s2 += __shfl_xor_sync(0xffffffffu, s2, m);
    }
    __syncthreads();                       // done reading xs; reuse for reduction
    if ((tid & 31) == 0) { xs[tid>>5] = s1; xs[8 + (tid>>5)] = s2; }
    __syncthreads();
    if (tid == 0) {
        float a1 = 0.0f, a2 = 0.0f;
        for (int i = 0; i < 8; i++) { a1 += xs[i]; a2 += xs[8+i]; }
        atomicAdd(&g_stats[co],    a1);
        atomicAdd(&g_stats[CH+co], a2);
    }
}

// ---------------------------------------------------------------------------
// BN (training batch stats) + PReLU, writing transposed feature fT (B,N,C).
__global__ void __launch_bounds__(256) k_bnt(const float* __restrict__ scale,
                                             const float* __restrict__ bias,
                                             const float* __restrict__ pa) {
    __shared__ float tile[64][65];
    __shared__ float msc[64], mof[64];
    const int b = blockIdx.y;
    const int i0 = blockIdx.x * 64;
    const int tid = threadIdx.x;
    const float a = pa[0];
    if (tid < 64) {
        const float inv = 1.0f / (float)(BATCH * NPIX);
        float m = g_stats[tid] * inv;
        float v = g_stats[CH + tid] * inv - m*m;
        float r = rsqrtf(v + 1e-5f);
        msc[tid] = r * scale[tid];
        mof[tid] = bias[tid] - m * r * scale[tid];
    }
    __syncthreads();
#pragma unroll
    for (int k = 0; k < 16; k++) {
        int idx = tid + k*256;
        int c = idx >> 6, ii = idx & 63;
        float v = g_y[(size_t)(b*CH + c)*NPIX + i0 + ii];
        v = v * msc[c] + mof[c];
        v = (v >= 0.0f) ? v : a * v;
        tile[c][ii] = v;
    }
    __syncthreads();
#pragma unroll
    for (int k = 0; k < 16; k++) {
        int idx = tid + k*256;
        int ii = idx >> 6, c = idx & 63;
        g_fT[((size_t)b*NPIX + i0 + ii)*CH + c] = tile[c][ii];
    }
}

// ---------------------------------------------------------------------------
// Flash attention: per block one (batch, 64-row i-tile). scores = -Q.K,
// online softmax, O += P.V with V = K tile. 256 threads, 4x4 micro-tiles.
// Smem: Qs [i][c-chunk] (float4), Ks chunked [c4][swizzled j] (float4),
// Ps [i][j-chunk] (float4). 48 KB dynamic.
__device__ __forceinline__ int jperm(int j) { return ((j & 7) << 3) | (j >> 3); }

__global__ void __launch_bounds__(256) k_attn(const float* __restrict__ gamma_p,
                                              float* __restrict__ out) {
    extern __shared__ float sm[];
    float4* Qs4 = reinterpret_cast<float4*>(sm);           // 1024 float4
    float4* Ks4 = reinterpret_cast<float4*>(sm + 4096);    // 1024 float4
    float4* Ps4 = reinterpret_cast<float4*>(sm + 8192);    // 1024 float4
    const float* Qsf = sm;

    const int b  = blockIdx.y;
    const int i0 = blockIdx.x * 64;
    const int tid = threadIdx.x;
    const int tx = tid & 15, ty = tid >> 4;

    const float4* fT4 = reinterpret_cast<const float4*>(g_fT + (size_t)b*NPIX*CH);

    // stage Q (rows i0..i0+63), layout Qs4[i*16 + c4]
#pragma unroll
    for (int k = 0; k < 4; k++) {
        int lin = tid + k*256;
        Qs4[lin] = fT4[(size_t)(i0 + (lin >> 4))*16 + (lin & 15)];
    }

    int pj[4];
#pragma unroll
    for (int q = 0; q < 4; q++) pj[q] = jperm(4*tx + q);

    float m[4], l[4], O[4][4];
#pragma unroll
    for (int r = 0; r < 4; r++) {
        m[r] = -INFINITY; l[r] = 0.0f;
#pragma unroll
        for (int e = 0; e < 4; e++) O[r][e] = 0.0f;
    }

    for (int jt = 0; jt < 64; jt++) {
        __syncthreads();   // prior PV finished before K overwrite
#pragma unroll
        for (int k = 0; k < 4; k++) {
            int lin = tid + k*256;
            int j = lin >> 4, c4 = lin & 15;
            Ks4[c4*64 + (jperm(j) ^ (c4 & 7))] = fT4[(size_t)(jt*64 + j)*16 + c4];
        }
        __syncthreads();

        // S = Q . K^T (accumulate dot, negate below)
        float acc[4][4];
#pragma unroll
        for (int r = 0; r < 4; r++)
#pragma unroll
            for (int q = 0; q < 4; q++) acc[r][q] = 0.0f;
#pragma unroll
        for (int c4 = 0; c4 < 16; c4++) {
            float4 qf[4], kf[4];
#pragma unroll
            for (int r = 0; r < 4; r++) qf[r] = Qs4[(4*ty + r)*16 + c4];
#pragma unroll
            for (int q = 0; q < 4; q++) kf[q] = Ks4[c4*64 + (pj[q] ^ (c4 & 7))];
#pragma unroll
            for (int r = 0; r < 4; r++)
#pragma unroll
                for (int q = 0; q < 4; q++) {
                    acc[r][q] += qf[r].x*kf[q].x + qf[r].y*kf[q].y
                               + qf[r].z*kf[q].z + qf[r].w*kf[q].w;
                }
        }

        // online softmax of s = -acc over j (row-wise across the 16 tx lanes)
#pragma unroll
        for (int r = 0; r < 4; r++) {
            float s0 = -acc[r][0], s1v = -acc[r][1], s2v = -acc[r][2], s3v = -acc[r][3];
            float lm = fmaxf(fmaxf(s0, s1v), fmaxf(s2v, s3v));
#pragma unroll
            for (int msk = 1; msk < 16; msk <<= 1)
                lm = fmaxf(lm, __shfl_xor_sync(0xffffffffu, lm, msk));
            float mn = fmaxf(m[r], lm);
            float alpha = __expf(m[r] - mn);
            float p0 = __expf(s0 - mn), p1 = __expf(s1v - mn);
            float p2 = __expf(s2v - mn), p3 = __expf(s3v - mn);
            float lp = p0 + p1 + p2 + p3;
#pragma unroll
            for (int msk = 1; msk < 16; msk <<= 1)
                lp += __shfl_xor_sync(0xffffffffu, lp, msk);
            l[r] = l[r] * alpha + lp;
            m[r] = mn;
#pragma unroll
            for (int e = 0; e < 4; e++) O[r][e] *= alpha;
            Ps4[(4*ty + r)*16 + tx] = make_float4(p0, p1, p2, p3);
        }
        __syncthreads();

        // O += P . V   (V[j][c] = K tile)
#pragma unroll
        for (int j4 = 0; j4 < 16; j4++) {
            float4 pf[4], vf[4];
#pragma unroll
            for (int r = 0; r < 4; r++) pf[r] = Ps4[(4*ty + r)*16 + j4];
#pragma unroll
            for (int jj = 0; jj < 4; jj++) {
                int j = 4*j4 + jj;
                vf[jj] = Ks4[tx*64 + (jperm(j) ^ (tx & 7))];
            }
#pragma unroll
            for (int r = 0; r < 4; r++) {
                O[r][0] += pf[r].x*vf[0].x + pf[r].y*vf[1].x + pf[r].z*vf[2].x + pf[r].w*vf[3].x;
                O[r][1] += pf[r].x*vf[0].y + pf[r].y*vf[1].y + pf[r].z*vf[2].y + pf[r].w*vf[3].y;
                O[r][2] += pf[r].x*vf[0].z + pf[r].y*vf[1].z + pf[r].z*vf[2].z + pf[r].w*vf[3].z;
                O[r][3] += pf[r].x*vf[0].w + pf[r].y*vf[1].w + pf[r].z*vf[2].w + pf[r].w*vf[3].w;
            }
        }
    }

    // epilogue: out[b][c][i] = gamma * O/l + feat   (feat read back from Qs)
    const float g = gamma_p[0];
    float ginv[4];
#pragma unroll
    for (int r = 0; r < 4; r++) ginv[r] = g / l[r];
#pragma unroll
    for (int e = 0; e < 4; e++) {
        int c = 4*tx + e;
        float4 v;
        v.x = O[0][e]*ginv[0] + Qsf[(4*ty + 0)*64 + c];
        v.y = O[1][e]*ginv[1] + Qsf[(4*ty + 1)*64 + c];
        v.z = O[2][e]*ginv[2] + Qsf[(4*ty + 2)*64 + c];
        v.w = O[3][e]*ginv[3] + Qsf[(4*ty + 3)*64 + c];
        float* dst = out + (size_t)(b*CH + c)*NPIX + i0 + 4*ty;
        *reinterpret_cast<float4*>(dst) = v;
    }
}

// ---------------------------------------------------------------------------
extern "C" void kernel_launch(void* const* d_in, const int* in_sizes, int n_in,
                              void* d_out, int out_size) {
    const float* x     = (const float*)d_in[0];
    const float* cw    = (const float*)d_in[1];
    const float* cb    = (const float*)d_in[2];
    const float* bns   = (const float*)d_in[3];
    const float* bnb   = (const float*)d_in[4];
    const float* pa    = (const float*)d_in[5];
    const float* gamma = (const float*)d_in[6];
    float* out = (float*)d_out;

    static bool attr_done = false;
    if (!attr_done) {
        cudaFuncSetAttribute(k_attn, cudaFuncAttributeMaxDynamicSharedMemorySize, 49152);
        attr_done = true;
    }

    k_init_stats<<<1, 128>>>();
    k_conv<<<dim3(CH, BATCH), 256>>>(x, cw, cb);
    k_bnt<<<dim3(64, BATCH), 256>>>(bns, bnb, pa);
    k_attn<<<dim3(64, BATCH), 256, 49152>>>(gamma, out);
}